// round 8
// baseline (speedup 1.0000x reference)
#include <cuda_runtime.h>
#include <cstdint>

// ---------------------------------------------------------------------------
// TernaryConv2d via int8 IMMA (m16n8k32) implicit GEMM, hi/lo split of x,
// tap-shift indexing, double-buffered cp.async pipeline.
// x: [32,128,56,56] f32, w: [256,128,3,3] f32, bias:[256] -> out:[32,256,54,54]
// ---------------------------------------------------------------------------

#define CC    128
#define HHH   56
#define WID   56
#define OCH   256
#define OHH   54
#define OWW   54
#define NN    32

#define NTHR   512
#define NCHUNK 4            // ic chunks of 32
#define BR     4            // staged rows (2 out + 2 halo)
#define BROWW  68           // words per staged row (64 data + 4 pad)
#define PLW    280          // words per icg plane (4*68 + 8 pad: bank-spread)
#define BW     (8 * PLW)    // words per array per chunk = 2240
#define A_W_CHUNK   (9 * 8 * 32 * 4)                 // 9216 uint32 = 36864 B
#define A_B_CHUNK   (A_W_CHUNK * 4)
#define STAGE_BYTES (A_B_CHUNK + 2 * BW * 4)         // 36864 + 17920 = 54784
#define SMEM_DYN    (2 * STAGE_BYTES)                // 109568

#define XPLANE (HHH * 64)                            // 3584 words per (n,icg)

__device__ __align__(16) uint32_t g_qwi[73728];      // int8 weights, frag order
__device__ __align__(16) uint32_t g_xhi[NN * 32 * XPLANE];   // 14.68 MB
__device__ __align__(16) uint32_t g_xlo[NN * 32 * XPLANE];
__device__ unsigned g_wmax_bits;
__device__ unsigned g_xmax_bits;

// ------------------------- preprocessing ----------------------------------
__global__ void k_init() { g_wmax_bits = 0u; g_xmax_bits = 0u; }

__device__ __forceinline__ void blk_absmax(float m, unsigned* dst) {
#pragma unroll
    for (int o = 16; o > 0; o >>= 1) m = fmaxf(m, __shfl_xor_sync(~0u, m, o));
    __shared__ float sm[32];
    int lane = threadIdx.x & 31, wd = threadIdx.x >> 5;
    if (lane == 0) sm[wd] = m;
    __syncthreads();
    if (threadIdx.x < 32) {
        int nw = (blockDim.x + 31) >> 5;
        m = (threadIdx.x < nw) ? sm[threadIdx.x] : 0.f;
#pragma unroll
        for (int o = 16; o > 0; o >>= 1) m = fmaxf(m, __shfl_xor_sync(~0u, m, o));
        if (threadIdx.x == 0) atomicMax(dst, __float_as_uint(m));
    }
}

__global__ void k_max(const float* __restrict__ w, int n) {
    float m = 0.f;
    for (int i = blockIdx.x * blockDim.x + threadIdx.x; i < n; i += gridDim.x * blockDim.x)
        m = fmaxf(m, fabsf(w[i]));
    blk_absmax(m, &g_wmax_bits);
}

__global__ void k_xmax(const float* __restrict__ x, int n4) {
    const float4* x4 = (const float4*)x;
    float m = 0.f;
    for (int i = blockIdx.x * blockDim.x + threadIdx.x; i < n4; i += gridDim.x * blockDim.x) {
        float4 v = x4[i];
        m = fmaxf(m, fmaxf(fmaxf(fabsf(v.x), fabsf(v.y)), fmaxf(fabsf(v.z), fabsf(v.w))));
    }
    blk_absmax(m, &g_xmax_bits);
}

// weights -> packed int8 in IMMA A-fragment order:
// g_qwi[(((half*4+chunk)*72 + tap*8 + mtile)*32 + lane)*4 + r], 4 consecutive ic per word
__global__ void k_quant(const float* __restrict__ w) {
    int idx = blockIdx.x * blockDim.x + threadIdx.x;
    if (idx >= 73728) return;
    int r    = idx & 3;
    int lane = (idx >> 2) & 31;
    int f    = idx >> 7;                 // (half*4+chunk)*72 + tap*8 + mtile
    int mtile = f & 7;
    int tap   = (f >> 3) % 9;
    int hc    = f / 72;                  // half*4 + chunk
    int half  = hc >> 2, chunk = hc & 3;
    int g = lane >> 2, t4 = lane & 3;
    int oc     = half * 128 + mtile * 16 + g + 8 * (r & 1);
    int icbase = chunk * 32 + (r >> 1) * 16 + t4 * 4;
    float t = 0.05f * __uint_as_float(g_wmax_bits);
    uint32_t packed = 0;
#pragma unroll
    for (int b = 0; b < 4; b++) {
        float wv = w[(oc * CC + icbase + b) * 9 + tap];
        int q = (wv > t) - (wv < -t);
        packed |= (uint32_t)(q & 0xFF) << (8 * b);
    }
    g_qwi[idx] = packed;
}

// x -> hi/lo int8 planes, layout [n][icg][h][w64] packed 4 channels/word
__global__ void k_xq(const float* __restrict__ x) {
    int idx = blockIdx.x * blockDim.x + threadIdx.x;
    if (idx >= NN * 32 * XPLANE) return;
    int wcol = idx & 63;
    int h    = (idx >> 6) % HHH;
    int icg  = (idx / (64 * HHH)) & 31;
    int n    = idx / (64 * HHH * 32);
    uint32_t ph = 0, pl = 0;
    if (wcol < WID) {
        const float inv = 127.f / __uint_as_float(g_xmax_bits);
#pragma unroll
        for (int c = 0; c < 4; c++) {
            float v = x[((size_t)(n * CC + icg * 4 + c) * HHH + h) * WID + wcol];
            float a  = v * inv;
            int   hi = __float2int_rn(a);
            int   lo = __float2int_rn((a - (float)hi) * 254.f);
            ph |= (uint32_t)(hi & 0xFF) << (8 * c);
            pl |= (uint32_t)(lo & 0xFF) << (8 * c);
        }
    }
    g_xhi[idx] = ph;
    g_xlo[idx] = pl;
}

// ------------------------- helpers -----------------------------------------
__device__ __forceinline__ void imma32(int* c, const uint4& a, uint32_t b0, uint32_t b1) {
    asm volatile(
        "mma.sync.aligned.m16n8k32.row.col.s32.s8.s8.s32 "
        "{%0,%1,%2,%3}, {%4,%5,%6,%7}, {%8,%9}, {%0,%1,%2,%3};"
        : "+r"(c[0]), "+r"(c[1]), "+r"(c[2]), "+r"(c[3])
        : "r"(a.x), "r"(a.y), "r"(a.z), "r"(a.w), "r"(b0), "r"(b1));
}

__device__ __forceinline__ uint32_t smem_u32(const void* p) {
    uint32_t a;
    asm("{ .reg .u64 t; cvta.to.shared.u64 t, %1; cvt.u32.u64 %0, t; }" : "=r"(a) : "l"(p));
    return a;
}

__device__ __forceinline__ void cpa16(uint32_t dst, const void* src) {
    asm volatile("cp.async.cg.shared.global [%0], [%1], 16;" :: "r"(dst), "l"(src) : "memory");
}

// stage one ic-chunk (A weights + B hi/lo) into stage buffer
__device__ __forceinline__ void stage_chunk(uint32_t sbase, int chunk, int half,
                                            int rg, int n, int tid) {
    const uint4* asrc = (const uint4*)(g_qwi + (size_t)(half * 4 + chunk) * A_W_CHUNK);
    for (int i = tid; i < A_W_CHUNK / 4; i += NTHR)           // 2304 x 16B
        cpa16(sbase + i * 16, asrc + i);
    const uint32_t bbase = sbase + A_B_CHUNK;
#pragma unroll
    for (int it = 0; it < 2; it++) {                          // 1024 x 16B
        int i   = it * NTHR + tid;
        int seg = i & 15;
        int row = (i >> 4) & 3;
        int icg = (i >> 6) & 7;
        int arr = i >> 9;
        const uint32_t* src = (arr ? g_xlo : g_xhi)
            + ((size_t)(n * 32 + chunk * 8 + icg) * HHH + (rg * 2 + row)) * 64 + seg * 4;
        cpa16(bbase + (arr * BW + icg * PLW + row * BROWW + seg * 4) * 4, src);
    }
    asm volatile("cp.async.commit_group;" ::: "memory");
}

// ------------------------- conv kernel --------------------------------------
// grid (2 oc-halves, 27 row-groups, 32 n), block 512 (warp_m 0..7, warp_n 0..1)
__global__ __launch_bounds__(NTHR, 1) void k_conv(const float* __restrict__ bias,
                                                  float* __restrict__ out) {
    extern __shared__ char smem[];
    const uint32_t sb = smem_u32(smem);

    const int tid    = threadIdx.x;
    const int wid    = tid >> 5;
    const int lane   = tid & 31;
    const int warp_m = wid & 7;
    const int warp_n = wid >> 3;
    const int g      = lane >> 2;
    const int t4     = lane & 3;
    const int half   = blockIdx.x;
    const int rg     = blockIdx.y;
    const int n      = blockIdx.z;

    int acch[8][4], accl[8][4];
#pragma unroll
    for (int ni = 0; ni < 8; ni++)
#pragma unroll
        for (int r = 0; r < 4; r++) { acch[ni][r] = 0; accl[ni][r] = 0; }

    stage_chunk(sb, 0, half, rg, n, tid);

    for (int chunk = 0; chunk < NCHUNK; chunk++) {
        asm volatile("cp.async.wait_group 0;" ::: "memory");
        __syncthreads();
        if (chunk + 1 < NCHUNK)
            stage_chunk(sb + ((chunk + 1) & 1) * STAGE_BYTES, chunk + 1, half, rg, n, tid);

        const char*     stg = smem + (chunk & 1) * STAGE_BYTES;
        const uint4*    Af  = (const uint4*)stg;
        const uint32_t* Bh0 = (const uint32_t*)(stg + A_B_CHUNK) + t4 * PLW;
        const uint32_t* Bh1 = Bh0 + 4 * PLW;
        const uint32_t* Bl0 = Bh0 + BW;
        const uint32_t* Bl1 = Bh1 + BW;

#pragma unroll
        for (int tap = 0; tap < 9; tap++) {
            const int kh = tap / 3, kw = tap - 3 * kh;
            const int pb = (warp_n + kh) * BROWW + g + kw;
            const uint4 a = Af[(tap * 8 + warp_m) * 32 + lane];
#pragma unroll
            for (int ni = 0; ni < 8; ni++) {
                const int p = pb + ni * 8;
                imma32(acch[ni], a, Bh0[p], Bh1[p]);
                imma32(accl[ni], a, Bl0[p], Bl1[p]);
            }
        }
    }

    // ---- epilogue: out = s/127*(hi + lo/254) + bias
    const float s   = __uint_as_float(g_xmax_bits);
    const float sc  = s / 127.f;
    const float scl = sc * (1.f / 254.f);
    const int oh  = rg * 2 + warp_n;                 // <= 53, always valid
    const int oc0 = half * 128 + warp_m * 16 + g;
    const float bv0 = bias[oc0], bv1 = bias[oc0 + 8];
    float* o0 = out + ((size_t)n * OCH + oc0) * (OHH * OWW) + oh * OWW;
    float* o1 = o0 + 8 * (OHH * OWW);
#pragma unroll
    for (int ni = 0; ni < 7; ni++) {
        const int ow = ni * 8 + 2 * t4;
        if (ow < OWW) {
            float2 v0, v1;
            v0.x = (float)acch[ni][0] * sc + (float)accl[ni][0] * scl + bv0;
            v0.y = (float)acch[ni][1] * sc + (float)accl[ni][1] * scl + bv0;
            v1.x = (float)acch[ni][2] * sc + (float)accl[ni][2] * scl + bv1;
            v1.y = (float)acch[ni][3] * sc + (float)accl[ni][3] * scl + bv1;
            *(float2*)(o0 + ow) = v0;
            *(float2*)(o1 + ow) = v1;
        }
    }
}

// ------------------------- launch -------------------------------------------
extern "C" void kernel_launch(void* const* d_in, const int* in_sizes, int n_in,
                              void* d_out, int out_size) {
    const float* x    = (const float*)d_in[0];
    const float* w    = (const float*)d_in[1];
    const float* bias = (const float*)d_in[2];
    float*       out  = (float*)d_out;

    k_init<<<1, 1>>>();
    k_max<<<256, 256>>>(w, OCH * CC * 9);
    k_xmax<<<1024, 256>>>(x, NN * CC * HHH * WID / 4);
    k_quant<<<(73728 + 255) / 256, 256>>>(w);
    k_xq<<<(NN * 32 * XPLANE + 255) / 256, 256>>>(x);

    cudaFuncSetAttribute(k_conv, cudaFuncAttributeMaxDynamicSharedMemorySize, SMEM_DYN);
    dim3 grid(2, 27, NN);
    k_conv<<<grid, NTHR, SMEM_DYN>>>(bias, out);

    (void)in_sizes; (void)n_in; (void)out_size;
}

// round 9
// speedup vs baseline: 3.0579x; 3.0579x over previous
#include <cuda_runtime.h>
#include <cstdint>

// ---------------------------------------------------------------------------
// TernaryConv2d via mma.sync (HMMA tf32) implicit GEMM, tap-shift indexing,
// double-buffered cp.async pipeline, 2 CTAs/SM, 7 n-frags (no wasted cols).
// x: [32,128,56,56] f32, w: [256,128,3,3] f32, bias:[256] -> out:[32,256,54,54]
// ---------------------------------------------------------------------------

#define CC    128
#define HHH   56
#define WID   56
#define OCH   256
#define OHH   54
#define OWW   54
#define NN    32

#define NTHR   256
#define ICK    8            // ic per chunk
#define NCHUNK 16
#define BROWS  4            // 2 out rows + 2 halo
#define BCOLS  68           // row stride in words (56 data + pad)
#define PLX    280          // per-ic plane stride in words (bank-spread: 280%32=24)
#define A_FLOATS_CHUNK (9 * 8 * 32 * 4)        // 9216 floats = 36864 B
#define A_BYTES_CHUNK  (A_FLOATS_CHUNK * 4)
#define B_WORDS        (ICK * PLX)             // 2240 words = 8960 B
#define STAGE_BYTES    (A_BYTES_CHUNK + B_WORDS * 4)   // 45824
#define SMEM_DYN       (2 * STAGE_BYTES)               // 91648

__device__ float    g_qw[2 * NCHUNK * A_FLOATS_CHUNK];   // 294912 floats
__device__ unsigned g_wmax_bits;

// ------------------------- preprocessing ----------------------------------
__global__ void k_init() { g_wmax_bits = 0u; }

__global__ void k_max(const float* __restrict__ w, int n) {
    float m = 0.f;
    for (int i = blockIdx.x * blockDim.x + threadIdx.x; i < n; i += gridDim.x * blockDim.x)
        m = fmaxf(m, fabsf(w[i]));
#pragma unroll
    for (int o = 16; o > 0; o >>= 1) m = fmaxf(m, __shfl_xor_sync(~0u, m, o));
    __shared__ float sm[32];
    int lane = threadIdx.x & 31, wd = threadIdx.x >> 5;
    if (lane == 0) sm[wd] = m;
    __syncthreads();
    if (threadIdx.x < 32) {
        int nw = (blockDim.x + 31) >> 5;
        m = (threadIdx.x < nw) ? sm[threadIdx.x] : 0.f;
#pragma unroll
        for (int o = 16; o > 0; o >>= 1) m = fmaxf(m, __shfl_xor_sync(~0u, m, o));
        if (threadIdx.x == 0) atomicMax(&g_wmax_bits, __float_as_uint(m));
    }
}

// quantize weights into mma A-fragment order for K=8 chunks:
// g_qw[(half*16+chunk)*9216 + ((tap*8+mtile)*32 + lane)*4 + r]
//   r0=(g,k) r1=(g+8,k) r2=(g,k+4) r3=(g+8,k+4); g=lane>>2, k=lane&3
__global__ void k_quant(const float* __restrict__ w) {
    int idx = blockIdx.x * blockDim.x + threadIdx.x;
    if (idx >= 2 * NCHUNK * A_FLOATS_CHUNK) return;
    int r     = idx & 3;
    int lane  = (idx >> 2) & 31;
    int f     = idx >> 7;
    int mtile = f & 7;
    int tap   = (f >> 3) % 9;
    int hc    = f / 72;               // half*16 + chunk
    int half  = hc >> 4, chunk = hc & 15;
    int oc = half * 128 + mtile * 16 + (lane >> 2) + 8 * (r & 1);
    int ic = chunk * ICK + (lane & 3) + 4 * (r >> 1);
    float t  = 0.05f * __uint_as_float(g_wmax_bits);
    float wv = w[(oc * CC + ic) * 9 + tap];
    g_qw[idx] = (wv > t ? 1.f : 0.f) - (wv < -t ? 1.f : 0.f);
}

// ------------------------- helpers -----------------------------------------
__device__ __forceinline__ void mma8(float* c, const float4& a, uint32_t b0, uint32_t b1) {
    const uint32_t* ai = (const uint32_t*)&a;
    asm volatile(
        "mma.sync.aligned.m16n8k8.row.col.f32.tf32.tf32.f32 "
        "{%0,%1,%2,%3}, {%4,%5,%6,%7}, {%8,%9}, {%0,%1,%2,%3};"
        : "+f"(c[0]), "+f"(c[1]), "+f"(c[2]), "+f"(c[3])
        : "r"(ai[0]), "r"(ai[1]), "r"(ai[2]), "r"(ai[3]), "r"(b0), "r"(b1));
}

__device__ __forceinline__ uint32_t smem_u32(const void* p) {
    uint32_t a;
    asm("{ .reg .u64 t; cvta.to.shared.u64 t, %1; cvt.u32.u64 %0, t; }" : "=r"(a) : "l"(p));
    return a;
}

__device__ __forceinline__ void cpa16(uint32_t dst, const void* src) {
    asm volatile("cp.async.cg.shared.global [%0], [%1], 16;" :: "r"(dst), "l"(src) : "memory");
}

// issue all cp.async for one ic-chunk into stage buffer at smem addr `sbase`
__device__ __forceinline__ void stage_chunk(uint32_t sbase, int chunk, int half,
                                            int rg, int tid, const float* xin) {
    // A: 2304 float4, linear, 9 per thread
    const float4* asrc = (const float4*)(g_qw + (size_t)(half * NCHUNK + chunk) * A_FLOATS_CHUNK);
#pragma unroll
    for (int i = 0; i < 9; i++) {
        int e = i * NTHR + tid;
        cpa16(sbase + e * 16, asrc + e);
    }
    // B: 8 ic x 4 rows x 14 float4 (cols 0..55); rows always in-bounds (rg<=26)
    const uint32_t bdst = sbase + A_BYTES_CHUNK;
    const int ic0 = chunk * ICK;
#pragma unroll
    for (int it = 0; it < 2; it++) {
        int i = it * NTHR + tid;
        if (i < ICK * BROWS * 14) {
            int c4  = i % 14;
            int row = (i / 14) & 3;
            int ic  = i / 56;
            const float4* s = (const float4*)(xin + (size_t)(ic0 + ic) * (HHH * WID)
                                              + (rg * 2 + row) * WID) + c4;
            cpa16(bdst + (ic * PLX + row * BCOLS + c4 * 4) * 4, s);
        }
    }
    asm volatile("cp.async.commit_group;" ::: "memory");
}

// ------------------------- conv kernel --------------------------------------
// grid (2 oc-halves, 27 row-groups, 32 n), block 256 (warp_m 0..3, warp_n 0..1)
__global__ __launch_bounds__(NTHR, 2) void k_conv(const float* __restrict__ x,
                                                  const float* __restrict__ bias,
                                                  float* __restrict__ out) {
    extern __shared__ char smem[];
    const uint32_t sb = smem_u32(smem);

    const int tid    = threadIdx.x;
    const int wid    = tid >> 5;
    const int lane   = tid & 31;
    const int warp_m = wid & 3;       // 32-oc group (2 mtiles)
    const int warp_n = wid >> 2;      // output row within row-group
    const int g      = lane >> 2;
    const int t4     = lane & 3;
    const int half   = blockIdx.x;
    const int rg     = blockIdx.y;
    const int n      = blockIdx.z;

    // one-time zero of both B regions (pad cols/plane pad never overwritten)
    for (int s = 0; s < 2; s++) {
        uint32_t* B = (uint32_t*)(smem + s * STAGE_BYTES + A_BYTES_CHUNK);
        for (int i = tid; i < B_WORDS; i += NTHR) B[i] = 0;
    }
    __syncthreads();

    float acc[2][7][4];
#pragma unroll
    for (int mi = 0; mi < 2; mi++)
#pragma unroll
        for (int ni = 0; ni < 7; ni++)
#pragma unroll
            for (int r = 0; r < 4; r++) acc[mi][ni][r] = 0.f;

    const float* xin = x + (size_t)n * CC * HHH * WID;

    stage_chunk(sb, 0, half, rg, tid, xin);

    for (int chunk = 0; chunk < NCHUNK; chunk++) {
        asm volatile("cp.async.wait_group 0;" ::: "memory");
        __syncthreads();
        if (chunk + 1 < NCHUNK)
            stage_chunk(sb + ((chunk + 1) & 1) * STAGE_BYTES, chunk + 1, half, rg, tid, xin);

        const char*     stg = smem + (chunk & 1) * STAGE_BYTES;
        const float4*   Af  = (const float4*)stg;
        const uint32_t* Bs  = (const uint32_t*)(stg + A_BYTES_CHUNK);
        const uint32_t* Bq0 = Bs + t4 * PLX;          // k = t4
        const uint32_t* Bq1 = Bs + (t4 + 4) * PLX;    // k = t4 + 4

#pragma unroll
        for (int tap = 0; tap < 9; tap++) {
            const int kh = tap / 3, kw = tap - 3 * kh;
            const int prow = (warp_n + kh) * BCOLS + g + kw;
            const int fbase = (tap * 8 + warp_m * 2) * 32 + lane;
            const float4 A0 = Af[fbase];
            const float4 A1 = Af[fbase + 32];
            const uint32_t* B0 = Bq0 + prow;
            const uint32_t* B1 = Bq1 + prow;
#pragma unroll
            for (int ni = 0; ni < 7; ni++) {
                uint32_t b0 = B0[ni * 8];
                uint32_t b1 = B1[ni * 8];
                mma8(acc[0][ni], A0, b0, b1);
                mma8(acc[1][ni], A1, b0, b1);
            }
        }
    }

    // ---- epilogue
    const int oh = rg * 2 + warp_n;    // always < 54
#pragma unroll
    for (int mi = 0; mi < 2; mi++) {
        const int oc0 = half * 128 + warp_m * 32 + mi * 16 + g;
        const float bv0 = bias[oc0];
        const float bv1 = bias[oc0 + 8];
        float* o0 = out + ((size_t)n * OCH + oc0) * (OHH * OWW) + oh * OWW;
        float* o1 = o0 + 8 * (OHH * OWW);
#pragma unroll
        for (int ni = 0; ni < 7; ni++) {
            const int ow = ni * 8 + 2 * t4;
            if (ow < OWW) {
                float2 v0 = make_float2(acc[mi][ni][0] + bv0, acc[mi][ni][1] + bv0);
                float2 v1 = make_float2(acc[mi][ni][2] + bv1, acc[mi][ni][3] + bv1);
                *(float2*)(o0 + ow) = v0;
                *(float2*)(o1 + ow) = v1;
            }
        }
    }
}

// ------------------------- launch -------------------------------------------
extern "C" void kernel_launch(void* const* d_in, const int* in_sizes, int n_in,
                              void* d_out, int out_size) {
    const float* x    = (const float*)d_in[0];
    const float* w    = (const float*)d_in[1];
    const float* bias = (const float*)d_in[2];
    float*       out  = (float*)d_out;

    k_init<<<1, 1>>>();
    k_max<<<256, 256>>>(w, OCH * CC * 9);
    k_quant<<<(2 * NCHUNK * A_FLOATS_CHUNK + 255) / 256, 256>>>(w);

    cudaFuncSetAttribute(k_conv, cudaFuncAttributeMaxDynamicSharedMemorySize, SMEM_DYN);
    dim3 grid(2, 27, NN);
    k_conv<<<grid, NTHR, SMEM_DYN>>>(x, bias, out);

    (void)in_sizes; (void)n_in; (void)out_size;
}

// round 10
// speedup vs baseline: 4.6983x; 1.5364x over previous
#include <cuda_runtime.h>
#include <cuda_fp16.h>
#include <cstdint>

// ---------------------------------------------------------------------------
// TernaryConv2d via mma.sync m16n8k16 (HMMA fp16, fp32 accum) implicit GEMM.
// Ternary weights are exact in fp16 => only error is fp16(x) rounding (~2.8e-4).
// Tap-shift indexing, double-buffered cp.async pipeline, 2 CTAs/SM.
// x: [32,128,56,56] f32, w: [256,128,3,3] f32, bias:[256] -> out:[32,256,54,54]
// ---------------------------------------------------------------------------

#define CC    128
#define HHH   56
#define WID   56
#define OCH   256
#define OHH   54
#define OWW   54
#define NN    32

#define NTHR   256
#define ICK    16           // ic per chunk (one k16 HMMA deep)
#define NCHUNK 8
#define BROWS  4            // 2 out rows + 2 halo
#define BCOLS  68           // row stride in half2 words (56 data + pad)
#define PLX    280          // per-icpair plane stride in words (280%32=24: bank-spread)
#define A_WORDS_CHUNK (9 * 8 * 32 * 4)         // 9216 words (half2) = 36864 B
#define A_BYTES_CHUNK (A_WORDS_CHUNK * 4)
#define B_WORDS       (8 * PLX)                // 8 icpair planes = 2240 words
#define STAGE_BYTES   (A_BYTES_CHUNK + B_WORDS * 4)    // 45824
#define SMEM_DYN      (2 * STAGE_BYTES)                // 91648

__device__ __align__(16) uint32_t g_qw[2 * NCHUNK * A_WORDS_CHUNK];  // 147456 words
__device__ __align__(16) uint32_t g_xh[NN * 64 * HHH * WID];         // half2 planes, 25.7 MB
__device__ unsigned g_wmax_bits;

// ------------------------- preprocessing ----------------------------------
__global__ void k_init() { g_wmax_bits = 0u; }

__global__ void k_max(const float* __restrict__ w, int n) {
    float m = 0.f;
    for (int i = blockIdx.x * blockDim.x + threadIdx.x; i < n; i += gridDim.x * blockDim.x)
        m = fmaxf(m, fabsf(w[i]));
#pragma unroll
    for (int o = 16; o > 0; o >>= 1) m = fmaxf(m, __shfl_xor_sync(~0u, m, o));
    __shared__ float sm[32];
    int lane = threadIdx.x & 31, wd = threadIdx.x >> 5;
    if (lane == 0) sm[wd] = m;
    __syncthreads();
    if (threadIdx.x < 32) {
        int nw = (blockDim.x + 31) >> 5;
        m = (threadIdx.x < nw) ? sm[threadIdx.x] : 0.f;
#pragma unroll
        for (int o = 16; o > 0; o >>= 1) m = fmaxf(m, __shfl_xor_sync(~0u, m, o));
        if (threadIdx.x == 0) atomicMax(&g_wmax_bits, __float_as_uint(m));
    }
}

// quantize weights into m16n8k16 A-fragment order, half2-packed:
// word idx = ((half*8+chunk)*72 + tap*8 + mtile)*32*4 + lane*4 + r
//  r0:(oc=g,      ic=2t4,2t4+1)   r1:(oc=g+8, same ic)
//  r2:(oc=g,      ic=2t4+8,+9)    r3:(oc=g+8, same ic)
__global__ void k_quant(const float* __restrict__ w) {
    int idx = blockIdx.x * blockDim.x + threadIdx.x;
    if (idx >= 2 * NCHUNK * A_WORDS_CHUNK) return;
    int r     = idx & 3;
    int lane  = (idx >> 2) & 31;
    int f     = idx >> 7;             // (half*8+chunk)*72 + tap*8 + mtile
    int mtile = f & 7;
    int tap   = (f >> 3) % 9;
    int hc    = f / 72;
    int half  = hc >> 3, chunk = hc & 7;
    int g  = lane >> 2, t4 = lane & 3;
    int oc  = half * 128 + mtile * 16 + g + 8 * (r & 1);
    int ic0 = chunk * ICK + 2 * t4 + 8 * (r >> 1);
    float t = 0.05f * __uint_as_float(g_wmax_bits);
    float w0 = w[(oc * CC + ic0) * 9 + tap];
    float w1 = w[(oc * CC + ic0 + 1) * 9 + tap];
    __half h0 = __float2half_rn((w0 > t ? 1.f : 0.f) - (w0 < -t ? 1.f : 0.f));
    __half h1 = __float2half_rn((w1 > t ? 1.f : 0.f) - (w1 < -t ? 1.f : 0.f));
    g_qw[idx] = (uint32_t)__half_as_ushort(h0) | ((uint32_t)__half_as_ushort(h1) << 16);
}

// x -> channel-pair packed half2 planes: g_xh[((n*64+icp)*56 + h)*56 + col]
__global__ void k_xh(const float* __restrict__ x) {
    int idx = blockIdx.x * blockDim.x + threadIdx.x;
    if (idx >= NN * 64 * HHH * WID) return;
    int col = idx % WID;
    int h   = (idx / WID) % HHH;
    int icp = (idx / (WID * HHH)) & 63;
    int n   = idx / (WID * HHH * 64);
    const float* p = x + ((size_t)(n * CC + icp * 2) * HHH + h) * WID + col;
    __half h0 = __float2half_rn(p[0]);
    __half h1 = __float2half_rn(p[HHH * WID]);
    g_xh[idx] = (uint32_t)__half_as_ushort(h0) | ((uint32_t)__half_as_ushort(h1) << 16);
}

// ------------------------- helpers -----------------------------------------
__device__ __forceinline__ void mma16(float* c, const uint4& a, uint32_t b0, uint32_t b1) {
    asm volatile(
        "mma.sync.aligned.m16n8k16.row.col.f32.f16.f16.f32 "
        "{%0,%1,%2,%3}, {%4,%5,%6,%7}, {%8,%9}, {%0,%1,%2,%3};"
        : "+f"(c[0]), "+f"(c[1]), "+f"(c[2]), "+f"(c[3])
        : "r"(a.x), "r"(a.y), "r"(a.z), "r"(a.w), "r"(b0), "r"(b1));
}

__device__ __forceinline__ uint32_t smem_u32(const void* p) {
    uint32_t a;
    asm("{ .reg .u64 t; cvta.to.shared.u64 t, %1; cvt.u32.u64 %0, t; }" : "=r"(a) : "l"(p));
    return a;
}

__device__ __forceinline__ void cpa16(uint32_t dst, const void* src) {
    asm volatile("cp.async.cg.shared.global [%0], [%1], 16;" :: "r"(dst), "l"(src) : "memory");
}

// issue all cp.async for one ic-chunk into stage buffer at smem addr `sbase`
__device__ __forceinline__ void stage_chunk(uint32_t sbase, int chunk, int half,
                                            int rg, int n, int tid) {
    // A: 2304 x 16B, linear
    const uint4* asrc = (const uint4*)(g_qw + (size_t)(half * NCHUNK + chunk) * A_WORDS_CHUNK);
#pragma unroll
    for (int i = 0; i < 9; i++) {
        int e = i * NTHR + tid;
        cpa16(sbase + e * 16, asrc + e);
    }
    // B: 8 icpair x 4 rows x 14 x 16B (cols 0..55); rows always in-bounds (rg<=26)
    const uint32_t bdst = sbase + A_BYTES_CHUNK;
#pragma unroll
    for (int it = 0; it < 2; it++) {
        int i = it * NTHR + tid;
        if (i < 8 * BROWS * 14) {
            int c4  = i % 14;
            int row = (i / 14) & 3;
            int icp = i / 56;
            const uint32_t* s = g_xh + ((size_t)(n * 64 + chunk * 8 + icp) * HHH
                                        + (rg * 2 + row)) * WID + c4 * 4;
            cpa16(bdst + (icp * PLX + row * BCOLS + c4 * 4) * 4, s);
        }
    }
    asm volatile("cp.async.commit_group;" ::: "memory");
}

// ------------------------- conv kernel --------------------------------------
// grid (2 oc-halves, 27 row-groups, 32 n), block 256 (warp_m 0..3, warp_n 0..1)
__global__ __launch_bounds__(NTHR, 2) void k_conv(const float* __restrict__ bias,
                                                  float* __restrict__ out) {
    extern __shared__ char smem[];
    const uint32_t sb = smem_u32(smem);

    const int tid    = threadIdx.x;
    const int wid    = tid >> 5;
    const int lane   = tid & 31;
    const int warp_m = wid & 3;
    const int warp_n = wid >> 2;
    const int g      = lane >> 2;
    const int t4     = lane & 3;
    const int half   = blockIdx.x;
    const int rg     = blockIdx.y;
    const int n      = blockIdx.z;

    // one-time zero of both B regions (halo cols 56..67 + plane pad stay zero)
    for (int s = 0; s < 2; s++) {
        uint32_t* B = (uint32_t*)(smem + s * STAGE_BYTES + A_BYTES_CHUNK);
        for (int i = tid; i < B_WORDS; i += NTHR) B[i] = 0;
    }
    __syncthreads();

    float acc[2][7][4];
#pragma unroll
    for (int mi = 0; mi < 2; mi++)
#pragma unroll
        for (int ni = 0; ni < 7; ni++)
#pragma unroll
            for (int r = 0; r < 4; r++) acc[mi][ni][r] = 0.f;

    stage_chunk(sb, 0, half, rg, n, tid);

    for (int chunk = 0; chunk < NCHUNK; chunk++) {
        asm volatile("cp.async.wait_group 0;" ::: "memory");
        __syncthreads();
        if (chunk + 1 < NCHUNK)
            stage_chunk(sb + ((chunk + 1) & 1) * STAGE_BYTES, chunk + 1, half, rg, n, tid);

        const char*     stg = smem + (chunk & 1) * STAGE_BYTES;
        const uint4*    Af  = (const uint4*)stg;
        const uint32_t* Bs  = (const uint32_t*)(stg + A_BYTES_CHUNK);
        const uint32_t* Bq0 = Bs + t4 * PLX;          // k pair t4   (ic 2t4,2t4+1)
        const uint32_t* Bq1 = Bs + (t4 + 4) * PLX;    // k pair t4+4 (ic 2t4+8,+9)

#pragma unroll
        for (int tap = 0; tap < 9; tap++) {
            const int kh = tap / 3, kw = tap - 3 * kh;
            const int prow = (warp_n + kh) * BCOLS + g + kw;
            const int fbase = (tap * 8 + warp_m * 2) * 32 + lane;
            const uint4 A0 = Af[fbase];
            const uint4 A1 = Af[fbase + 32];
            const uint32_t* B0 = Bq0 + prow;
            const uint32_t* B1 = Bq1 + prow;
#pragma unroll
            for (int ni = 0; ni < 7; ni++) {
                uint32_t b0 = B0[ni * 8];
                uint32_t b1 = B1[ni * 8];
                mma16(acc[0][ni], A0, b0, b1);
                mma16(acc[1][ni], A1, b0, b1);
            }
        }
    }

    // ---- epilogue
    const int oh = rg * 2 + warp_n;    // always < 54
#pragma unroll
    for (int mi = 0; mi < 2; mi++) {
        const int oc0 = half * 128 + warp_m * 32 + mi * 16 + g;
        const float bv0 = bias[oc0];
        const float bv1 = bias[oc0 + 8];
        float* o0 = out + ((size_t)n * OCH + oc0) * (OHH * OWW) + oh * OWW;
        float* o1 = o0 + 8 * (OHH * OWW);
#pragma unroll
        for (int ni = 0; ni < 7; ni++) {
            const int ow = ni * 8 + 2 * t4;
            if (ow < OWW) {
                float2 v0 = make_float2(acc[mi][ni][0] + bv0, acc[mi][ni][1] + bv0);
                float2 v1 = make_float2(acc[mi][ni][2] + bv1, acc[mi][ni][3] + bv1);
                *(float2*)(o0 + ow) = v0;
                *(float2*)(o1 + ow) = v1;
            }
        }
    }
}

// ------------------------- launch -------------------------------------------
extern "C" void kernel_launch(void* const* d_in, const int* in_sizes, int n_in,
                              void* d_out, int out_size) {
    const float* x    = (const float*)d_in[0];
    const float* w    = (const float*)d_in[1];
    const float* bias = (const float*)d_in[2];
    float*       out  = (float*)d_out;

    k_init<<<1, 1>>>();
    k_max<<<256, 256>>>(w, OCH * CC * 9);
    k_quant<<<(2 * NCHUNK * A_WORDS_CHUNK + 255) / 256, 256>>>(w);
    k_xh<<<(NN * 64 * HHH * WID + 255) / 256, 256>>>(x);

    cudaFuncSetAttribute(k_conv, cudaFuncAttributeMaxDynamicSharedMemorySize, SMEM_DYN);
    dim3 grid(2, 27, NN);
    k_conv<<<grid, NTHR, SMEM_DYN>>>(bias, out);

    (void)in_sizes; (void)n_in; (void)out_size;
}